// round 10
// baseline (speedup 1.0000x reference)
#include <cuda_runtime.h>
#include <cuda_fp16.h>
#include <cstdint>

// MorphLayer == conv2d(x, exp(k1)-exp(k2), VALID 3x3) + bias  (exact reduction)
// B=32 C=64 H=W=64 -> Ho=Wo=62, F=128.
// HMMA implicit-GEMM, single fp16 product, fp32 acc.
// ROUND 10: 384-thread CTAs (12 warps, 1 CTA/SM, 148 CTAs), warp tile
// 64(w) x 64(f) -> 128 smem bytes per MMA (A 4 + B 4 LDSM4 feed 32 MMAs).
// CTA job: M=384 (6 oh x 64 w) x N=128; weights fully resident (144KB);
// 8-slot rolling row ring (slot = gh & 7). Jobs: 11 h-tiles x 32 bz = 352.

#define Hn  64
#define Wn  64
#define HOn 62
#define WOn 62
#define Fn  128
#define Cn  64

#define SLAB_ROWS  514                     // 8 slots * 64 + 2 overflow pad rows
#define SLAB_BYTES (SLAB_ROWS * 128)       // 65792
#define WOFF       SLAB_BYTES
#define WRES_BYTES (9 * 128 * 128)         // 147456
#define SMEM_TOTAL (WOFF + WRES_BYTES)     // 213248 -> 1 CTA/SM

#define NCTA    148
#define HTILES  11                         // ceil(62/6)
#define NJOBS   (HTILES * 32)              // 352

// fp16 weights, SW128-swizzled: [tap][f=128][c=64]
__device__ __align__(16) unsigned char g_W[9 * 16384];

__device__ __forceinline__ uint32_t smem_u32(const void* p) {
    uint32_t a;
    asm("{ .reg .u64 t; cvta.to.shared.u64 t, %1; cvt.u32.u64 %0, t; }" : "=r"(a) : "l"(p));
    return a;
}

#define LDSM4(r, addr)                                                          \
    asm volatile("ldmatrix.sync.aligned.m8n8.x4.shared.b16 {%0,%1,%2,%3}, [%4];" \
                 : "=r"((r)[0]), "=r"((r)[1]), "=r"((r)[2]), "=r"((r)[3])        \
                 : "r"(addr))

#define MMA(d, a, b0, b1)                                                       \
    asm volatile("mma.sync.aligned.m16n8k16.row.col.f32.f16.f16.f32 "           \
                 "{%0,%1,%2,%3}, {%4,%5,%6,%7}, {%8,%9}, {%0,%1,%2,%3};"        \
                 : "+f"((d)[0]), "+f"((d)[1]), "+f"((d)[2]), "+f"((d)[3])        \
                 : "r"((a)[0]), "r"((a)[1]), "r"((a)[2]), "r"((a)[3]),           \
                   "r"(b0), "r"(b1))

// ---------------- weight prep: w = exp(k1)-exp(k2) -> fp16, swizzled ----------------
__global__ void prep_w(const float* __restrict__ k1, const float* __restrict__ k2) {
    int idx = blockIdx.x * 256 + threadIdx.x;       // 73728 = 9*128*64
    int t   = idx >> 13;
    int rem = idx & 8191;
    int f   = rem >> 6;
    int c   = rem & 63;
    int src = (t * 64 + c) * 128 + f;               // k1 layout (kh,kw,C,F)
    float w = expf(k1[src]) - expf(k2[src]);
    __half h = __float2half_rn(w);
    unsigned off = (unsigned)(f * 128 + c * 2);
    off = off ^ ((off >> 3) & 0x70);                // SW128 swizzle
    *(unsigned short*)(g_W + t * 16384 + off) = *(unsigned short*)&h;
}

// ---------------- main kernel ----------------
extern __shared__ char smem_raw[];

__device__ __forceinline__ void build_rows(const float* __restrict__ xb,
                                           char* smem, int tid,
                                           int gh0, int nrows) {
    const int total = nrows * 512;     // 512 tasks per row (64 w x 8 c-groups)
    #pragma unroll 1
    for (int t = tid; t < total; t += 384) {
        int gw = t & 63;
        int cg = (t >> 6) & 7;
        int gh = gh0 + (t >> 9);
        unsigned short hs[8];
        if (gh < Hn) {
            const float* xp = xb + (size_t)(cg * 8) * (Hn * Wn) + gh * Wn + gw;
            #pragma unroll
            for (int i = 0; i < 8; i++) {
                __half h = __float2half_rn(xp[(size_t)i * (Hn * Wn)]);
                hs[i] = *(unsigned short*)&h;
            }
        } else {
            #pragma unroll
            for (int i = 0; i < 8; i++) hs[i] = 0;
        }
        unsigned row  = (unsigned)((gh & 7) * 64 + gw);     // ring slot
        unsigned boff = row * 128 + cg * 16;
        unsigned sw   = boff ^ ((boff >> 3) & 0x70);
        *(uint4*)(smem + sw) =
            make_uint4((uint32_t)hs[0] | ((uint32_t)hs[1] << 16),
                       (uint32_t)hs[2] | ((uint32_t)hs[3] << 16),
                       (uint32_t)hs[4] | ((uint32_t)hs[5] << 16),
                       (uint32_t)hs[6] | ((uint32_t)hs[7] << 16));
    }
}

__global__ void __launch_bounds__(384, 1)
conv_hmma_kernel(const float* __restrict__ x,
                 const float* __restrict__ bias,
                 float* __restrict__ out) {
    const int tid  = threadIdx.x;
    const int lane = tid & 31;
    const int wid  = tid >> 5;         // 0..11
    const int wn   = wid & 1;          // f 64-half
    const int wm   = wid >> 1;         // output row within job: oh = h0 + wm (0..5)
    const int cid  = blockIdx.x;

    int jstart, jcount;
    if (cid < 56) { jstart = cid * 3;              jcount = 3; }
    else          { jstart = 168 + (cid - 56) * 2; jcount = 2; }

    const uint32_t sb = smem_u32(smem_raw);

    // ---- resident weight load: all 128 filters x 9 taps (144KB) ----
    {
        #pragma unroll
        for (int j = 0; j < 24; j++) {
            int k = tid + j * 384;                  // 9216 chunks of 16B
            uint32_t dst = sb + WOFF + (uint32_t)k * 16;
            asm volatile("cp.async.cg.shared.global [%0], [%1], 16;"
                         :: "r"(dst), "l"(g_W + (size_t)k * 16));
        }
        asm volatile("cp.async.commit_group;");
    }

    // zero overflow pad rows 512..513 (feeds only discarded ow>=62 outputs)
    if (tid < 16) {
        *(uint4*)(smem_raw + 512 * 128 + tid * 16) = make_uint4(0u, 0u, 0u, 0u);
    }

    // lane-constant addressing
    const uint32_t a_hi16  = (uint32_t)(lane >> 4) * 16;
    const int      fb0     = wn * 64 + (lane & 7) + ((lane >> 4) & 1) * 8;
    const uint32_t b_off16 = (uint32_t)((lane >> 3) & 1) * 16;
    const uint32_t swzB    = (uint32_t)(fb0 & 7) << 4;
    const uint32_t wBase   = sb + WOFF + (uint32_t)fb0 * 128;
    const int      arow    = lane & 15;            // w base within slot

    // ---- build slab for first job (8 rows) ----
    {
        int bz0 = jstart / HTILES;
        int ht0 = jstart - bz0 * HTILES;
        build_rows(x + (size_t)bz0 * Cn * Hn * Wn, smem_raw, tid, 6 * ht0, 8);
    }
    asm volatile("cp.async.wait_group 0;");

    #pragma unroll 1
    for (int jj = 0; jj < jcount; jj++) {
        const int j  = jstart + jj;
        const int bz = j / HTILES;
        const int ht = j - bz * HTILES;
        const int h0 = 6 * ht;

        __syncthreads();               // slab (+ weights on first job) visible

        float acc[4][8][4];            // [mi(w16)][ni(f8)][quad] = 128 regs
        #pragma unroll
        for (int mi = 0; mi < 4; mi++)
            #pragma unroll
            for (int ni = 0; ni < 8; ni++)
                #pragma unroll
                for (int q = 0; q < 4; q++) acc[mi][ni][q] = 0.0f;

        #pragma unroll 1
        for (int t = 0; t < 9; t++) {
            const int ki = t / 3;
            const int kj = t - 3 * ki;
            const int gh = h0 + wm + ki;
            const int sbase = (gh & 7) * 64 + arow + kj;
            const uint32_t swzA  = (uint32_t)(sbase & 7) << 4;
            const uint32_t aBase = sb + (uint32_t)sbase * 128;
            const uint32_t bTap  = wBase + (uint32_t)t * 16384;

            #pragma unroll
            for (int kc = 0; kc < 4; kc++) {
                const uint32_t aoff = ((uint32_t)(kc * 32) + a_hi16) ^ swzA;
                const uint32_t boff = ((uint32_t)(kc * 32) + b_off16) ^ swzB;

                uint32_t Bf[4][4];
                #pragma unroll
                for (int bi = 0; bi < 4; bi++)
                    LDSM4(Bf[bi], bTap + bi * 2048 + boff);

                #pragma unroll
                for (int mi = 0; mi < 4; mi++) {
                    uint32_t A[4];
                    LDSM4(A, aBase + mi * 2048 + aoff);
                    #pragma unroll
                    for (int bi = 0; bi < 4; bi++) {
                        MMA(acc[mi][2 * bi],     A, Bf[bi][0], Bf[bi][1]);
                        MMA(acc[mi][2 * bi + 1], A, Bf[bi][2], Bf[bi][3]);
                    }
                }
            }
        }

        __syncthreads();               // all reads done; ring slots reusable

        // ---- build slab rows for next job (overlaps epilogue) ----
        if (jj + 1 < jcount) {
            const int nj  = j + 1;
            const int nbz = nj / HTILES;
            const int nht = nj - nbz * HTILES;
            const float* nxb = x + (size_t)nbz * Cn * Hn * Wn;
            if (nht != 0) build_rows(nxb, smem_raw, tid, 6 * nht + 2, 6);
            else          build_rows(nxb, smem_raw, tid, 0, 8);
        }

        // ---- epilogue: acc -> out[bz, f, oh, ow] + bias ----
        const int oh = h0 + wm;
        if (oh < HOn) {
            #pragma unroll
            for (int ni = 0; ni < 8; ni++) {
                const int f = wn * 64 + ni * 8 + (lane & 3) * 2;
                const float b0 = __ldg(bias + f);
                const float b1 = __ldg(bias + f + 1);
                float* p0 = out + (((size_t)bz * Fn + f) * HOn + oh) * WOn;
                float* p1 = p0 + (size_t)HOn * WOn;
                #pragma unroll
                for (int mi = 0; mi < 4; mi++) {
                    const int w0 = mi * 16 + (lane >> 2);   // <= 55, always valid
                    const int w1 = w0 + 8;
                    p0[w0] = acc[mi][ni][0] + b0;
                    p1[w0] = acc[mi][ni][1] + b1;
                    if (w1 < WOn) {
                        p0[w1] = acc[mi][ni][2] + b0;
                        p1[w1] = acc[mi][ni][3] + b1;
                    }
                }
            }
        }
    }
}

extern "C" void kernel_launch(void* const* d_in, const int* in_sizes, int n_in,
                              void* d_out, int out_size) {
    const float* x    = (const float*)d_in[0];   // (32,64,64,64)
    const float* k1   = (const float*)d_in[1];   // (3,3,64,128)
    const float* k2   = (const float*)d_in[2];   // (3,3,64,128)
    const float* bias = (const float*)d_in[3];   // (128,)
    float* out = (float*)d_out;                  // (32,128,62,62)
    (void)in_sizes; (void)n_in; (void)out_size;

    cudaFuncSetAttribute(conv_hmma_kernel,
                         cudaFuncAttributeMaxDynamicSharedMemorySize, SMEM_TOTAL);

    prep_w<<<288, 256>>>(k1, k2);
    conv_hmma_kernel<<<NCTA, 384, SMEM_TOTAL>>>(x, bias, out);
}

// round 11
// speedup vs baseline: 1.3674x; 1.3674x over previous
#include <cuda_runtime.h>
#include <cuda_fp16.h>
#include <cstdint>

// MorphLayer == conv2d(x, exp(k1)-exp(k2), VALID 3x3) + bias  (exact reduction)
// B=32 C=64 H=W=64 -> Ho=Wo=62, F=128.
// HMMA implicit-GEMM, single fp16 product, fp32 acc.
// R11 = R7 (best: 68us) + register double-buffered pipeline over the 36
// kc-steps: LDSM for step s+1 issued before MMAs of step s; buffer index is
// statically kc&1. Warp tile 32x32 keeps regs ~110 (<128 cap @ 2 CTA/SM).

#define Hn  64
#define Wn  64
#define HOn 62
#define WOn 62
#define Fn  128
#define Cn  64

#define SLAB_ROWS  258                     // 4 ring slots * 64 + 2 pad rows
#define SLAB_BYTES (SLAB_ROWS * 128)       // 33024
#define WOFF       SLAB_BYTES
#define WRES_BYTES (9 * 64 * 128)          // 73728
#define SMEM_TOTAL (WOFF + WRES_BYTES)     // 106752 -> 2 CTAs/SM

#define JOBS_PER_HALF 992                  // 31 h-tiles * 32 batch
#define NCTA_PER_HALF 148
#define JOBS_PER_CTA  7

// fp16 weights, SW128-swizzled: [tap][f=128][c=64]
__device__ __align__(16) unsigned char g_W[9 * 16384];

__device__ __forceinline__ uint32_t smem_u32(const void* p) {
    uint32_t a;
    asm("{ .reg .u64 t; cvta.to.shared.u64 t, %1; cvt.u32.u64 %0, t; }" : "=r"(a) : "l"(p));
    return a;
}

#define LDSM4(r, addr)                                                          \
    asm volatile("ldmatrix.sync.aligned.m8n8.x4.shared.b16 {%0,%1,%2,%3}, [%4];" \
                 : "=r"((r)[0]), "=r"((r)[1]), "=r"((r)[2]), "=r"((r)[3])        \
                 : "r"(addr))

#define MMA(d, a, b0, b1)                                                       \
    asm volatile("mma.sync.aligned.m16n8k16.row.col.f32.f16.f16.f32 "           \
                 "{%0,%1,%2,%3}, {%4,%5,%6,%7}, {%8,%9}, {%0,%1,%2,%3};"        \
                 : "+f"((d)[0]), "+f"((d)[1]), "+f"((d)[2]), "+f"((d)[3])        \
                 : "r"((a)[0]), "r"((a)[1]), "r"((a)[2]), "r"((a)[3]),           \
                   "r"(b0), "r"(b1))

// ---------------- weight prep ----------------
__global__ void prep_w(const float* __restrict__ k1, const float* __restrict__ k2) {
    int idx = blockIdx.x * 256 + threadIdx.x;       // 73728 = 9*128*64
    int t   = idx >> 13;
    int rem = idx & 8191;
    int f   = rem >> 6;
    int c   = rem & 63;
    int src = (t * 64 + c) * 128 + f;               // k1 layout (kh,kw,C,F)
    float w = expf(k1[src]) - expf(k2[src]);
    __half h = __float2half_rn(w);
    unsigned off = (unsigned)(f * 128 + c * 2);
    off = off ^ ((off >> 3) & 0x70);                // SW128 swizzle
    *(unsigned short*)(g_W + t * 16384 + off) = *(unsigned short*)&h;
}

// ---------------- main kernel ----------------
extern __shared__ char smem_raw[];

__device__ __forceinline__ void build_rows(const float* __restrict__ xb,
                                           char* smem, int tid,
                                           int gh0, int nrows) {
    #pragma unroll 1
    for (int it = 0; it < 2 * nrows; it++) {
        int t    = tid + it * 256;
        int gw   = t & 63;
        int cg   = (t >> 6) & 7;
        int gh   = gh0 + (t >> 9);
        const float* xp = xb + (size_t)(cg * 8) * (Hn * Wn) + gh * Wn + gw;
        unsigned short hs[8];
        #pragma unroll
        for (int i = 0; i < 8; i++) {
            __half h = __float2half_rn(xp[(size_t)i * (Hn * Wn)]);
            hs[i] = *(unsigned short*)&h;
        }
        unsigned row  = (unsigned)((gh & 3) * 64 + gw);     // ring slot
        unsigned boff = row * 128 + cg * 16;
        unsigned sw   = boff ^ ((boff >> 3) & 0x70);
        *(uint4*)(smem + sw) =
            make_uint4((uint32_t)hs[0] | ((uint32_t)hs[1] << 16),
                       (uint32_t)hs[2] | ((uint32_t)hs[3] << 16),
                       (uint32_t)hs[4] | ((uint32_t)hs[5] << 16),
                       (uint32_t)hs[6] | ((uint32_t)hs[7] << 16));
    }
}

__global__ void __launch_bounds__(256, 2)
conv_hmma_kernel(const float* __restrict__ x,
                 const float* __restrict__ bias,
                 float* __restrict__ out) {
    const int tid  = threadIdx.x;
    const int lane = tid & 31;
    const int wid  = tid >> 5;
    const int wm   = wid & 3;          // M block: oh = wm>>1, w-half = wm&1
    const int wn   = wid >> 2;         // N block: 32 filters
    const int fh   = blockIdx.x;       // filter half
    const int cid  = blockIdx.y;

    const int jstart = cid * JOBS_PER_CTA;
    if (jstart >= JOBS_PER_HALF) return;
    const int jend = (jstart + JOBS_PER_CTA < JOBS_PER_HALF)
                   ? jstart + JOBS_PER_CTA : JOBS_PER_HALF;

    const uint32_t sb = smem_u32(smem_raw);

    // ---- resident weight load: 64 filters x 9 taps (72KB), once per CTA ----
    {
        const unsigned char* src = g_W + fh * 8192;
        #pragma unroll
        for (int j = 0; j < 18; j++) {
            int k = tid + j * 256;
            int tap = k >> 9;
            int rem = k & 511;
            uint32_t dst = sb + WOFF + (uint32_t)k * 16;
            asm volatile("cp.async.cg.shared.global [%0], [%1], 16;"
                         :: "r"(dst), "l"(src + (size_t)tap * 16384 + rem * 16));
        }
        asm volatile("cp.async.commit_group;");
    }

    // zero pad rows 256..257 (feeds only discarded outputs)
    if (tid < 16) {
        *(uint4*)(smem_raw + 256 * 128 + tid * 16) = make_uint4(0u, 0u, 0u, 0u);
    }

    // lane-constant addressing
    const int      a_lrow  = lane & 15;
    const uint32_t a_hi16  = (uint32_t)(lane >> 4) * 16;
    const int      fb0     = wn * 32 + (lane & 7) + ((lane >> 4) & 1) * 8;
    const uint32_t b_off16 = (uint32_t)((lane >> 3) & 1) * 16;
    const uint32_t swzB    = (uint32_t)(fb0 & 7) << 4;
    const uint32_t wBase   = sb + WOFF + (uint32_t)fb0 * 128;
    const int      mrow0   = (wm & 1) * 32 + a_lrow;

    // bias hoisted
    float bv0[4], bv1[4];
    #pragma unroll
    for (int ni = 0; ni < 4; ni++) {
        const int f = fh * 64 + wn * 32 + ni * 8 + (lane & 3) * 2;
        bv0[ni] = __ldg(bias + f);
        bv1[ni] = __ldg(bias + f + 1);
    }

    // ---- build slab for first job ----
    int j0bz = jstart / 31;
    int j0ht = jstart - j0bz * 31;
    build_rows(x + (size_t)j0bz * Cn * Hn * Wn, smem_raw, tid, 2 * j0ht, 4);
    asm volatile("cp.async.wait_group 0;");

    #pragma unroll 1
    for (int j = jstart; j < jend; j++) {
        const int bz = j / 31;
        const int ht = j - bz * 31;
        const int h0 = 2 * ht;

        __syncthreads();               // slab writes visible

        float acc[2][4][4];
        #pragma unroll
        for (int mi = 0; mi < 2; mi++)
            #pragma unroll
            for (int ni = 0; ni < 4; ni++)
                #pragma unroll
                for (int q = 0; q < 4; q++) acc[mi][ni][q] = 0.0f;

        // fragment double buffers (index = kc&1, statically resolved)
        uint32_t Af[2][2][4], Bf[2][2][4];

        // preamble: load step (t=0, kc=0) into buf 0
        {
            const int sbase = ((h0 + (wm >> 1)) & 3) * 64 + mrow0;   // ki=0,kj=0
            const uint32_t swzA  = (uint32_t)(sbase & 7) << 4;
            const uint32_t aB    = sb + (uint32_t)sbase * 128;
            const uint32_t aoff  = a_hi16 ^ swzA;
            const uint32_t boff  = b_off16 ^ swzB;
            LDSM4(Af[0][0], aB + aoff);
            LDSM4(Af[0][1], aB + 2048 + aoff);
            LDSM4(Bf[0][0], wBase + boff);
            LDSM4(Bf[0][1], wBase + 2048 + boff);
        }

        #pragma unroll 1
        for (int t = 0; t < 9; t++) {
            const int ki = t / 3;
            const int kj = t - 3 * ki;
            const int sbase = ((h0 + (wm >> 1) + ki) & 3) * 64 + mrow0 + kj;
            const uint32_t swzA  = (uint32_t)(sbase & 7) << 4;
            const uint32_t aBase = sb + (uint32_t)sbase * 128;
            const uint32_t bTap  = wBase + (uint32_t)t * 8192;

            // next tap bases (t=8 -> dummy self; prefetched frags unused)
            const int tn  = (t < 8) ? t + 1 : 8;
            const int nki = tn / 3;
            const int nkj = tn - 3 * nki;
            const int nsb = ((h0 + (wm >> 1) + nki) & 3) * 64 + mrow0 + nkj;
            const uint32_t nswzA  = (uint32_t)(nsb & 7) << 4;
            const uint32_t naBase = sb + (uint32_t)nsb * 128;
            const uint32_t nbTap  = wBase + (uint32_t)tn * 8192;

            #pragma unroll
            for (int kc = 0; kc < 4; kc++) {
                const int cur = kc & 1;
                const int nxt = cur ^ 1;
                // ---- prefetch step+1 fragments ----
                const uint32_t pa   = (kc < 3) ? aBase : naBase;
                const uint32_t pb   = (kc < 3) ? bTap  : nbTap;
                const uint32_t pswz = (kc < 3) ? swzA  : nswzA;
                const uint32_t pkc  = (kc < 3) ? (uint32_t)((kc + 1) * 32) : 0u;
                const uint32_t aoffn = (pkc + a_hi16) ^ pswz;
                const uint32_t boffn = (pkc + b_off16) ^ swzB;
                LDSM4(Af[nxt][0], pa + aoffn);
                LDSM4(Af[nxt][1], pa + 2048 + aoffn);
                LDSM4(Bf[nxt][0], pb + boffn);
                LDSM4(Bf[nxt][1], pb + 2048 + boffn);

                // ---- MMAs on current buffer ----
                #pragma unroll
                for (int mi = 0; mi < 2; mi++)
                    #pragma unroll
                    for (int bi = 0; bi < 2; bi++) {
                        MMA(acc[mi][2 * bi],     Af[cur][mi], Bf[cur][bi][0], Bf[cur][bi][1]);
                        MMA(acc[mi][2 * bi + 1], Af[cur][mi], Bf[cur][bi][2], Bf[cur][bi][3]);
                    }
            }
        }

        __syncthreads();               // all reads done; slab reusable

        // ---- build slab rows for next job (overlaps epilogue) ----
        if (j + 1 < jend) {
            const int nbz = (j + 1) / 31;
            const int nht = (j + 1) - nbz * 31;
            const float* nxb = x + (size_t)nbz * Cn * Hn * Wn;
            if (nht != 0) build_rows(nxb, smem_raw, tid, 2 * nht + 2, 2);
            else          build_rows(nxb, smem_raw, tid, 0, 4);
        }

        // ---- epilogue ----
        const int oh  = h0 + (wm >> 1);
        const int wpx = (wm & 1) * 32;
        #pragma unroll
        for (int ni = 0; ni < 4; ni++) {
            const int f = fh * 64 + wn * 32 + ni * 8 + (lane & 3) * 2;
            float* p0 = out + (((size_t)bz * Fn + f) * HOn + oh) * WOn;
            float* p1 = p0 + (size_t)HOn * WOn;
            #pragma unroll
            for (int mi = 0; mi < 2; mi++) {
                const int w0 = wpx + mi * 16 + (lane >> 2);
                const int w1 = w0 + 8;
                p0[w0] = acc[mi][ni][0] + bv0[ni];
                p1[w0] = acc[mi][ni][1] + bv1[ni];
                if (w1 < WOn) {
                    p0[w1] = acc[mi][ni][2] + bv0[ni];
                    p1[w1] = acc[mi][ni][3] + bv1[ni];
                }
            }
        }
    }
}

extern "C" void kernel_launch(void* const* d_in, const int* in_sizes, int n_in,
                              void* d_out, int out_size) {
    const float* x    = (const float*)d_in[0];   // (32,64,64,64)
    const float* k1   = (const float*)d_in[1];   // (3,3,64,128)
    const float* k2   = (const float*)d_in[2];   // (3,3,64,128)
    const float* bias = (const float*)d_in[3];   // (128,)
    float* out = (float*)d_out;                  // (32,128,62,62)
    (void)in_sizes; (void)n_in; (void)out_size;

    cudaFuncSetAttribute(conv_hmma_kernel,
                         cudaFuncAttributeMaxDynamicSharedMemorySize, SMEM_TOTAL);

    prep_w<<<288, 256>>>(k1, k2);
    dim3 grid(2, NCTA_PER_HALF);       // 296 CTAs = one full wave at 2/SM
    conv_hmma_kernel<<<grid, 256, SMEM_TOTAL>>>(x, bias, out);
}